// round 1
// baseline (speedup 1.0000x reference)
#include <cuda_runtime.h>
#include <math.h>

// Problem constants
#define BB 2
#define TT 2048
#define HH 16
#define DD 64      // HEAD
#define MM 1024    // D_MODEL

// Scratch (device globals; no allocation allowed)
__device__ float g_A[HH * DD * DD];          // A_h = Wq_h Wk_h^T / 8   [h][d][d']
__device__ float g_U[MM * MM];               // U[h*64+d][n] = sum_m Wv[h][d][m] Wo[h*M+m][n]
__device__ float g_y[BB * HH * TT * DD];     // y[bh][t][d'] = xh @ A_h
__device__ float g_z[BB * TT * MM];          // z[b][t][h*64+d] = softmax(y xh^T) @ xh

// ---------------------------------------------------------------------------
// Kernel 1: A_h = (Wq_h @ Wk_h^T) * 0.125     (16 GEMMs 64x64x1024)
// grid: 16 (h), block: 256
// ---------------------------------------------------------------------------
__global__ void __launch_bounds__(256) computeA(const float* __restrict__ Wq,
                                                const float* __restrict__ Wk) {
    const int h = blockIdx.x;
    const int tid = threadIdx.x;
    const int tx = tid & 15;   // j group
    const int ty = tid >> 4;   // i group

    __shared__ float wqs[64 * 65];
    __shared__ float wks[64 * 65];

    float acc[4][4];
#pragma unroll
    for (int i = 0; i < 4; i++)
#pragma unroll
        for (int j = 0; j < 4; j++) acc[i][j] = 0.f;

    const float* wqh = Wq + (size_t)h * DD * MM;
    const float* wkh = Wk + (size_t)h * DD * MM;

    for (int m0 = 0; m0 < MM; m0 += 64) {
        __syncthreads();
#pragma unroll
        for (int c = 0; c < 4; c++) {
            int fi = tid + c * 256;      // 0..1023 float4 index
            int i = fi >> 4;             // 0..63
            int q = fi & 15;             // 0..15
            float4 a = *(const float4*)(wqh + i * MM + m0 + q * 4);
            wqs[i * 65 + q * 4 + 0] = a.x;
            wqs[i * 65 + q * 4 + 1] = a.y;
            wqs[i * 65 + q * 4 + 2] = a.z;
            wqs[i * 65 + q * 4 + 3] = a.w;
            float4 b = *(const float4*)(wkh + i * MM + m0 + q * 4);
            wks[i * 65 + q * 4 + 0] = b.x;
            wks[i * 65 + q * 4 + 1] = b.y;
            wks[i * 65 + q * 4 + 2] = b.z;
            wks[i * 65 + q * 4 + 3] = b.w;
        }
        __syncthreads();

        for (int m = 0; m < 64; m++) {
            float a[4], b[4];
#pragma unroll
            for (int i = 0; i < 4; i++) a[i] = wqs[(ty * 4 + i) * 65 + m];
#pragma unroll
            for (int j = 0; j < 4; j++) b[j] = wks[(tx * 4 + j) * 65 + m];
#pragma unroll
            for (int i = 0; i < 4; i++)
#pragma unroll
                for (int j = 0; j < 4; j++) acc[i][j] += a[i] * b[j];
        }
    }

    float* out = g_A + h * DD * DD;
#pragma unroll
    for (int i = 0; i < 4; i++)
#pragma unroll
        for (int j = 0; j < 4; j++)
            out[(ty * 4 + i) * DD + tx * 4 + j] = acc[i][j] * 0.125f;
}

// ---------------------------------------------------------------------------
// Kernel 2: U[h*64+d][n] = sum_m Wv[h][d][m] * Wo[h*M+m][n]
// grid: (8 col-tiles of 128, 16 h), block: 256; tile 64 rows x 128 cols
// ---------------------------------------------------------------------------
__global__ void __launch_bounds__(256) computeU(const float* __restrict__ Wv,
                                                const float* __restrict__ Wo) {
    const int h = blockIdx.y;
    const int col0 = blockIdx.x * 128;
    const int tid = threadIdx.x;
    const int tx = tid & 31;   // cols tx + 32*j
    const int ty = tid >> 5;   // rows ty*8 + i

    __shared__ float at[32 * 66];    // at[k][i]  (Wv chunk transposed)
    __shared__ float bs[32 * 128];   // bs[k][j]

    float acc[8][4];
#pragma unroll
    for (int i = 0; i < 8; i++)
#pragma unroll
        for (int j = 0; j < 4; j++) acc[i][j] = 0.f;

    const float* wvh = Wv + (size_t)h * DD * MM;
    const float* woh = Wo + (size_t)h * MM * MM;

    for (int m0 = 0; m0 < MM; m0 += 32) {
        __syncthreads();
#pragma unroll
        for (int c = 0; c < 2; c++) {
            int fi = tid + c * 256;      // 0..511
            int i = fi >> 3;             // 0..63
            int kq = fi & 7;             // 0..7
            float4 a = *(const float4*)(wvh + i * MM + m0 + kq * 4);
            at[(kq * 4 + 0) * 66 + i] = a.x;
            at[(kq * 4 + 1) * 66 + i] = a.y;
            at[(kq * 4 + 2) * 66 + i] = a.z;
            at[(kq * 4 + 3) * 66 + i] = a.w;
        }
#pragma unroll
        for (int c = 0; c < 4; c++) {
            int fi = tid + c * 256;      // 0..1023
            int kk = fi >> 5;            // 0..31
            int q = fi & 31;             // 0..31
            float4 b = *(const float4*)(woh + (size_t)(m0 + kk) * MM + col0 + q * 4);
            *(float4*)(bs + kk * 128 + q * 4) = b;
        }
        __syncthreads();

        for (int k = 0; k < 32; k++) {
            float a[8], b[4];
#pragma unroll
            for (int i = 0; i < 8; i++) a[i] = at[k * 66 + ty * 8 + i];
#pragma unroll
            for (int j = 0; j < 4; j++) b[j] = bs[k * 128 + tx + 32 * j];
#pragma unroll
            for (int i = 0; i < 8; i++)
#pragma unroll
                for (int j = 0; j < 4; j++) acc[i][j] += a[i] * b[j];
        }
    }

#pragma unroll
    for (int i = 0; i < 8; i++)
#pragma unroll
        for (int j = 0; j < 4; j++)
            g_U[(size_t)(h * 64 + ty * 8 + i) * MM + col0 + tx + 32 * j] = acc[i][j];
}

// ---------------------------------------------------------------------------
// Kernel 3: y[bh][t][d'] = sum_d x[b][t][h*64+d] * A[h][d][d']
// grid: (T/64 = 32, B*H = 32), block 256; tile 64 rows x 64 cols
// ---------------------------------------------------------------------------
__global__ void __launch_bounds__(256) computeY(const float* __restrict__ x) {
    const int t0 = blockIdx.x * 64;
    const int bh = blockIdx.y;
    const int b = bh >> 4;
    const int h = bh & 15;
    const int tid = threadIdx.x;
    const int tx = tid & 15;   // cols tx*4 + c
    const int ty = tid >> 4;   // rows ty*4 + i

    __shared__ float As[64 * 66];   // As[d][d']
    __shared__ float xs[64 * 65];   // xs[r][d]

    const float* ah = g_A + h * DD * DD;
#pragma unroll
    for (int c = 0; c < 4; c++) {
        int fi = tid + c * 256;   // 0..1023
        int d = fi >> 4;
        int q = fi & 15;
        float4 a = *(const float4*)(ah + d * 64 + q * 4);
        As[d * 66 + q * 4 + 0] = a.x;
        As[d * 66 + q * 4 + 1] = a.y;
        As[d * 66 + q * 4 + 2] = a.z;
        As[d * 66 + q * 4 + 3] = a.w;
    }
    const float* xb = x + ((size_t)b * TT + t0) * MM + h * 64;
#pragma unroll
    for (int c = 0; c < 4; c++) {
        int fi = tid + c * 256;   // 0..1023
        int r = fi >> 4;          // 0..63
        int q = fi & 15;
        float4 v = *(const float4*)(xb + (size_t)r * MM + q * 4);
        xs[r * 65 + q * 4 + 0] = v.x;
        xs[r * 65 + q * 4 + 1] = v.y;
        xs[r * 65 + q * 4 + 2] = v.z;
        xs[r * 65 + q * 4 + 3] = v.w;
    }
    __syncthreads();

    float acc[4][4];
#pragma unroll
    for (int i = 0; i < 4; i++)
#pragma unroll
        for (int c = 0; c < 4; c++) acc[i][c] = 0.f;

    for (int d = 0; d < 64; d++) {
        float a[4], bfr[4];
#pragma unroll
        for (int i = 0; i < 4; i++) a[i] = xs[(ty * 4 + i) * 65 + d];
#pragma unroll
        for (int c = 0; c < 4; c++) bfr[c] = As[d * 66 + tx * 4 + c];
#pragma unroll
        for (int i = 0; i < 4; i++)
#pragma unroll
            for (int c = 0; c < 4; c++) acc[i][c] += a[i] * bfr[c];
    }

    float* yb = g_y + ((size_t)bh * TT + t0) * DD;
#pragma unroll
    for (int i = 0; i < 4; i++) {
        float4 o = make_float4(acc[i][0], acc[i][1], acc[i][2], acc[i][3]);
        *(float4*)(yb + (size_t)(ty * 4 + i) * DD + tx * 4) = o;
    }
}

// ---------------------------------------------------------------------------
// Kernel 4: flash attention, K = V = xh_h, Q = y.  z[b][t][h*64+d]
// grid: (T/128 = 16, B*H = 32), block 256, dynamic smem 166400 B
// ---------------------------------------------------------------------------
#define FLASH_SMEM (size_t)((2 * 64 * 129 + 128 * 68 + 128 * 128) * 4)

__global__ void __launch_bounds__(256, 1) flashKernel(const float* __restrict__ x) {
    const int tid = threadIdx.x;
    const int tx = tid & 15;   // S cols tx + 16*j ; acc cols tx*4 + c
    const int ty = tid >> 4;   // rows ty*8 + i
    const int t0 = blockIdx.x * 128;
    const int bh = blockIdx.y;
    const int b = bh >> 4;
    const int h = bh & 15;

    extern __shared__ float sm[];
    float* Qt = sm;                       // [64][129]  Qt[d][t]
    float* Kt = sm + 64 * 129;            // [64][129]  Kt[d][s]
    float* Vs = sm + 2 * 64 * 129;        // [128][68]  Vs[s][d]
    float* Ps = sm + 2 * 64 * 129 + 128 * 68;  // [128][128]

    // Load Q tile (transposed) from g_y
    const float* yb = g_y + ((size_t)bh * TT + t0) * DD;
#pragma unroll
    for (int c = 0; c < 8; c++) {
        int fi = tid + c * 256;   // 0..2047
        int tl = fi >> 4;         // 0..127
        int q = fi & 15;
        float4 v = *(const float4*)(yb + (size_t)tl * DD + q * 4);
        Qt[(q * 4 + 0) * 129 + tl] = v.x;
        Qt[(q * 4 + 1) * 129 + tl] = v.y;
        Qt[(q * 4 + 2) * 129 + tl] = v.z;
        Qt[(q * 4 + 3) * 129 + tl] = v.w;
    }

    float acc[8][4];
    float mrow[8], lrow[8];
#pragma unroll
    for (int i = 0; i < 8; i++) {
        mrow[i] = -INFINITY;
        lrow[i] = 0.f;
#pragma unroll
        for (int c = 0; c < 4; c++) acc[i][c] = 0.f;
    }

    const float* xb = x + (size_t)b * TT * MM + h * 64;

    for (int s0 = 0; s0 < TT; s0 += 128) {
        __syncthreads();   // previous gemm2 done; also covers Q-load on iter 0
        // Load K/V tile (K transposed, V row-major)
#pragma unroll
        for (int c = 0; c < 8; c++) {
            int fi = tid + c * 256;
            int sl = fi >> 4;
            int q = fi & 15;
            float4 v = *(const float4*)(xb + (size_t)(s0 + sl) * MM + q * 4);
            Kt[(q * 4 + 0) * 129 + sl] = v.x;
            Kt[(q * 4 + 1) * 129 + sl] = v.y;
            Kt[(q * 4 + 2) * 129 + sl] = v.z;
            Kt[(q * 4 + 3) * 129 + sl] = v.w;
            *(float4*)(Vs + sl * 68 + q * 4) = v;
        }
        __syncthreads();

        // GEMM1: S = Q @ K^T (inner dim 64)
        float sfrag[8][8];
#pragma unroll
        for (int i = 0; i < 8; i++)
#pragma unroll
            for (int j = 0; j < 8; j++) sfrag[i][j] = 0.f;

        for (int d = 0; d < 64; d++) {
            float a[8], bfr[8];
#pragma unroll
            for (int i = 0; i < 8; i++) a[i] = Qt[d * 129 + ty * 8 + i];
#pragma unroll
            for (int j = 0; j < 8; j++) bfr[j] = Kt[d * 129 + tx + 16 * j];
#pragma unroll
            for (int i = 0; i < 8; i++)
#pragma unroll
                for (int j = 0; j < 8; j++) sfrag[i][j] += a[i] * bfr[j];
        }

        // Online softmax update (row groups of 16 lanes share rows)
#pragma unroll
        for (int i = 0; i < 8; i++) {
            float mx = sfrag[i][0];
#pragma unroll
            for (int j = 1; j < 8; j++) mx = fmaxf(mx, sfrag[i][j]);
#pragma unroll
            for (int o = 8; o >= 1; o >>= 1)
                mx = fmaxf(mx, __shfl_xor_sync(0xffffffffu, mx, o));
            float mnew = fmaxf(mrow[i], mx);
            float scale = __expf(mrow[i] - mnew);
            mrow[i] = mnew;
            float rs = 0.f;
#pragma unroll
            for (int j = 0; j < 8; j++) {
                float p = __expf(sfrag[i][j] - mnew);
                sfrag[i][j] = p;
                rs += p;
            }
#pragma unroll
            for (int o = 8; o >= 1; o >>= 1)
                rs += __shfl_xor_sync(0xffffffffu, rs, o);
            lrow[i] = lrow[i] * scale + rs;
#pragma unroll
            for (int c = 0; c < 4; c++) acc[i][c] *= scale;
        }

        // Write P to SMEM
#pragma unroll
        for (int i = 0; i < 8; i++)
#pragma unroll
            for (int j = 0; j < 8; j++)
                Ps[(ty * 8 + i) * 128 + tx + 16 * j] = sfrag[i][j];
        __syncthreads();

        // GEMM2: acc += P @ V  (V = K tile)
        for (int s = 0; s < 128; s++) {
            float4 v = *(const float4*)(Vs + s * 68 + tx * 4);
#pragma unroll
            for (int i = 0; i < 8; i++) {
                float p = Ps[(ty * 8 + i) * 128 + s];
                acc[i][0] += p * v.x;
                acc[i][1] += p * v.y;
                acc[i][2] += p * v.z;
                acc[i][3] += p * v.w;
            }
        }
    }

    // Write z (normalized), laid out [b][t][h*64+d] for the epilogue GEMM
    float* zb = g_z + ((size_t)b * TT + t0) * MM + h * 64;
#pragma unroll
    for (int i = 0; i < 8; i++) {
        float inv = 1.f / lrow[i];
        float4 o = make_float4(acc[i][0] * inv, acc[i][1] * inv,
                               acc[i][2] * inv, acc[i][3] * inv);
        *(float4*)(zb + (size_t)(ty * 8 + i) * MM + tx * 4) = o;
    }
}

// ---------------------------------------------------------------------------
// Kernel 5: out = z @ U + bo    (4096 x 1024 x 1024)
// grid: (8 col-tiles, 32 row-tiles), block 256; tile 128x128, micro 8x8
// ---------------------------------------------------------------------------
__global__ void __launch_bounds__(256) gemmOut(const float* __restrict__ bo,
                                               float* __restrict__ out) {
    const int col0 = blockIdx.x * 128;
    const int row0 = blockIdx.y * 128;
    const int tid = threadIdx.x;
    const int tx = tid & 15;   // cols tx + 16*j
    const int ty = tid >> 4;   // rows ty*8 + i

    __shared__ float zt[32 * 132];   // zt[k][r]
    __shared__ float us[32 * 128];   // us[k][col]

    float acc[8][8];
#pragma unroll
    for (int i = 0; i < 8; i++)
#pragma unroll
        for (int j = 0; j < 8; j++) acc[i][j] = 0.f;

    for (int k0 = 0; k0 < MM; k0 += 32) {
        __syncthreads();
#pragma unroll
        for (int c = 0; c < 4; c++) {
            int fi = tid + c * 256;   // 0..1023
            int r = fi >> 3;          // 0..127
            int kq = fi & 7;          // 0..7
            float4 a = *(const float4*)(g_z + (size_t)(row0 + r) * MM + k0 + kq * 4);
            zt[(kq * 4 + 0) * 132 + r] = a.x;
            zt[(kq * 4 + 1) * 132 + r] = a.y;
            zt[(kq * 4 + 2) * 132 + r] = a.z;
            zt[(kq * 4 + 3) * 132 + r] = a.w;
        }
#pragma unroll
        for (int c = 0; c < 4; c++) {
            int fi = tid + c * 256;
            int kk = fi >> 5;         // 0..31
            int q = fi & 31;          // 0..31
            float4 u = *(const float4*)(g_U + (size_t)(k0 + kk) * MM + col0 + q * 4);
            *(float4*)(us + kk * 128 + q * 4) = u;
        }
        __syncthreads();

        for (int k = 0; k < 32; k++) {
            float a[8], bfr[8];
#pragma unroll
            for (int i = 0; i < 8; i++) a[i] = zt[k * 132 + ty * 8 + i];
#pragma unroll
            for (int j = 0; j < 8; j++) bfr[j] = us[k * 128 + tx + 16 * j];
#pragma unroll
            for (int i = 0; i < 8; i++)
#pragma unroll
                for (int j = 0; j < 8; j++) acc[i][j] += a[i] * bfr[j];
        }
    }

    float bj[8];
#pragma unroll
    for (int j = 0; j < 8; j++) bj[j] = bo[col0 + tx + 16 * j];
#pragma unroll
    for (int i = 0; i < 8; i++)
#pragma unroll
        for (int j = 0; j < 8; j++)
            out[(size_t)(row0 + ty * 8 + i) * MM + col0 + tx + 16 * j] = acc[i][j] + bj[j];
}

// ---------------------------------------------------------------------------
extern "C" void kernel_launch(void* const* d_in, const int* in_sizes, int n_in,
                              void* d_out, int out_size) {
    const float* x  = (const float*)d_in[0];
    const float* Wq = (const float*)d_in[1];
    const float* Wk = (const float*)d_in[2];
    const float* Wv = (const float*)d_in[3];
    const float* Wo = (const float*)d_in[4];
    const float* bo = (const float*)d_in[5];
    float* out = (float*)d_out;

    cudaFuncSetAttribute(flashKernel, cudaFuncAttributeMaxDynamicSharedMemorySize,
                         (int)FLASH_SMEM);

    computeA<<<16, 256>>>(Wq, Wk);
    computeU<<<dim3(8, 16), 256>>>(Wv, Wo);
    computeY<<<dim3(TT / 64, BB * HH), 256>>>(x);
    flashKernel<<<dim3(TT / 128, BB * HH), 256, FLASH_SMEM>>>(x);
    gemmOut<<<dim3(MM / 128, (BB * TT) / 128), 256>>>(bo, out);
}